// round 1
// baseline (speedup 1.0000x reference)
#include <cuda_runtime.h>

// LoRALayerNorm: x [B=2, S=4096, N=8192] fp32
// scale[i] = SCALING * sum_r A_s[i,r] * B_s[r,i]
// shift[i] = SCALING * sum_r A_h[i,r] * B_h[r,i]
// out = layernorm(x, last dim) * scale + shift

#define N_FEAT 8192
#define N_ROWS 8192
#define RANK 4
#define SCALING_F 2.0f   // ALPHA/RANK = 8/4
#define EPS_F 1e-5f

#define TPB 512                 // threads per block (row kernel)
#define VEC_PER_THREAD 4        // 4 x float4 = 16 floats/thread; 512*16 = 8192

__device__ float g_scale[N_FEAT];
__device__ float g_shift[N_FEAT];

// ---------------------------------------------------------------------------
// Kernel 1: low-rank diagonal -> scale/shift vectors
// ---------------------------------------------------------------------------
__global__ void compute_vectors_kernel(const float* __restrict__ sA,
                                       const float* __restrict__ sB,
                                       const float* __restrict__ hA,
                                       const float* __restrict__ hB) {
    int i = blockIdx.x * blockDim.x + threadIdx.x;
    if (i >= N_FEAT) return;
    // A: [N, RANK] row-major; B: [RANK, N] row-major
    float4 a_s = *reinterpret_cast<const float4*>(sA + i * RANK);
    float4 a_h = *reinterpret_cast<const float4*>(hA + i * RANK);
    float sc = a_s.x * sB[0 * N_FEAT + i]
             + a_s.y * sB[1 * N_FEAT + i]
             + a_s.z * sB[2 * N_FEAT + i]
             + a_s.w * sB[3 * N_FEAT + i];
    float sh = a_h.x * hB[0 * N_FEAT + i]
             + a_h.y * hB[1 * N_FEAT + i]
             + a_h.z * hB[2 * N_FEAT + i]
             + a_h.w * hB[3 * N_FEAT + i];
    g_scale[i] = sc * SCALING_F;
    g_shift[i] = sh * SCALING_F;
}

// ---------------------------------------------------------------------------
// Kernel 2: one CTA per row, register-resident single-pass layernorm
// ---------------------------------------------------------------------------
__global__ __launch_bounds__(TPB, 2)
void lora_layernorm_kernel(const float* __restrict__ x,
                           float* __restrict__ out) {
    const int row = blockIdx.x;
    const int tid = threadIdx.x;
    const float4* xrow = reinterpret_cast<const float4*>(x + (size_t)row * N_FEAT);
    float4* orow = reinterpret_cast<float4*>(out + (size_t)row * N_FEAT);

    // Load 4 float4 per thread, strided across the row for coalescing.
    float4 v[VEC_PER_THREAD];
    float sum = 0.0f, sumsq = 0.0f;
#pragma unroll
    for (int k = 0; k < VEC_PER_THREAD; k++) {
        float4 t = xrow[tid + k * TPB];
        v[k] = t;
        sum += t.x + t.y + t.z + t.w;
        sumsq += t.x * t.x + t.y * t.y + t.z * t.z + t.w * t.w;
    }

    // Warp reduce
#pragma unroll
    for (int off = 16; off > 0; off >>= 1) {
        sum += __shfl_xor_sync(0xffffffffu, sum, off);
        sumsq += __shfl_xor_sync(0xffffffffu, sumsq, off);
    }

    __shared__ float s_sum[TPB / 32];
    __shared__ float s_sumsq[TPB / 32];
    __shared__ float s_mean, s_rstd;
    const int wid = tid >> 5;
    const int lane = tid & 31;
    if (lane == 0) {
        s_sum[wid] = sum;
        s_sumsq[wid] = sumsq;
    }
    __syncthreads();
    if (wid == 0) {
        float a = (lane < TPB / 32) ? s_sum[lane] : 0.0f;
        float b = (lane < TPB / 32) ? s_sumsq[lane] : 0.0f;
#pragma unroll
        for (int off = 8; off > 0; off >>= 1) {
            a += __shfl_xor_sync(0xffffffffu, a, off);
            b += __shfl_xor_sync(0xffffffffu, b, off);
        }
        if (lane == 0) {
            float mean = a * (1.0f / N_FEAT);
            float var = b * (1.0f / N_FEAT) - mean * mean;
            s_mean = mean;
            s_rstd = rsqrtf(var + EPS_F);
        }
    }
    __syncthreads();
    const float mean = s_mean;
    const float rstd = s_rstd;

    // Epilogue: x_hat * scale + shift
    const float4* scv = reinterpret_cast<const float4*>(g_scale);
    const float4* shv = reinterpret_cast<const float4*>(g_shift);
#pragma unroll
    for (int k = 0; k < VEC_PER_THREAD; k++) {
        int idx = tid + k * TPB;
        float4 sc = scv[idx];
        float4 sh = shv[idx];
        float4 t = v[k];
        float4 o;
        o.x = (t.x - mean) * rstd * sc.x + sh.x;
        o.y = (t.y - mean) * rstd * sc.y + sh.y;
        o.z = (t.z - mean) * rstd * sc.z + sh.z;
        o.w = (t.w - mean) * rstd * sc.w + sh.w;
        orow[idx] = o;
    }
}

// ---------------------------------------------------------------------------
extern "C" void kernel_launch(void* const* d_in, const int* in_sizes, int n_in,
                              void* d_out, int out_size) {
    const float* x = (const float*)d_in[0];
    const float* sA = (const float*)d_in[1];
    const float* sB = (const float*)d_in[2];
    const float* hA = (const float*)d_in[3];
    const float* hB = (const float*)d_in[4];
    float* out = (float*)d_out;

    compute_vectors_kernel<<<N_FEAT / 256, 256>>>(sA, sB, hA, hB);
    lora_layernorm_kernel<<<N_ROWS, TPB>>>(x, out);
}

// round 2
// speedup vs baseline: 1.0023x; 1.0023x over previous
#include <cuda_runtime.h>

// LoRALayerNorm: x [B=2, S=4096, N=8192] fp32
// scale[i] = SCALING * sum_r A_s[i,r] * B_s[r,i]
// shift[i] = SCALING * sum_r A_h[i,r] * B_h[r,i]
// out = layernorm(x, last dim) * scale + shift

#define N_FEAT 8192
#define N_ROWS 8192
#define RANK 4
#define SCALING_F 2.0f   // ALPHA/RANK = 8/4
#define EPS_F 1e-5f

#define TPB 512                 // threads per block (row kernel)
#define VEC_PER_THREAD 4        // 4 x float4 = 16 floats/thread; 512*16 = 8192

__device__ float g_scale[N_FEAT];
__device__ float g_shift[N_FEAT];

// ---------------------------------------------------------------------------
// Kernel 1: low-rank diagonal -> scale/shift vectors
// ---------------------------------------------------------------------------
__global__ void compute_vectors_kernel(const float* __restrict__ sA,
                                       const float* __restrict__ sB,
                                       const float* __restrict__ hA,
                                       const float* __restrict__ hB) {
    int i = blockIdx.x * blockDim.x + threadIdx.x;
    if (i >= N_FEAT) return;
    // A: [N, RANK] row-major; B: [RANK, N] row-major
    float4 a_s = *reinterpret_cast<const float4*>(sA + i * RANK);
    float4 a_h = *reinterpret_cast<const float4*>(hA + i * RANK);
    float sc = a_s.x * sB[0 * N_FEAT + i]
             + a_s.y * sB[1 * N_FEAT + i]
             + a_s.z * sB[2 * N_FEAT + i]
             + a_s.w * sB[3 * N_FEAT + i];
    float sh = a_h.x * hB[0 * N_FEAT + i]
             + a_h.y * hB[1 * N_FEAT + i]
             + a_h.z * hB[2 * N_FEAT + i]
             + a_h.w * hB[3 * N_FEAT + i];
    g_scale[i] = sc * SCALING_F;
    g_shift[i] = sh * SCALING_F;
}

// ---------------------------------------------------------------------------
// Kernel 2: one CTA per row, register-resident single-pass layernorm
// ---------------------------------------------------------------------------
__global__ __launch_bounds__(TPB, 2)
void lora_layernorm_kernel(const float* __restrict__ x,
                           float* __restrict__ out) {
    const int row = blockIdx.x;
    const int tid = threadIdx.x;
    const float4* xrow = reinterpret_cast<const float4*>(x + (size_t)row * N_FEAT);
    float4* orow = reinterpret_cast<float4*>(out + (size_t)row * N_FEAT);

    // Load 4 float4 per thread, strided across the row for coalescing.
    float4 v[VEC_PER_THREAD];
    float sum = 0.0f, sumsq = 0.0f;
#pragma unroll
    for (int k = 0; k < VEC_PER_THREAD; k++) {
        float4 t = xrow[tid + k * TPB];
        v[k] = t;
        sum += t.x + t.y + t.z + t.w;
        sumsq += t.x * t.x + t.y * t.y + t.z * t.z + t.w * t.w;
    }

    // Warp reduce
#pragma unroll
    for (int off = 16; off > 0; off >>= 1) {
        sum += __shfl_xor_sync(0xffffffffu, sum, off);
        sumsq += __shfl_xor_sync(0xffffffffu, sumsq, off);
    }

    __shared__ float s_sum[TPB / 32];
    __shared__ float s_sumsq[TPB / 32];
    __shared__ float s_mean, s_rstd;
    const int wid = tid >> 5;
    const int lane = tid & 31;
    if (lane == 0) {
        s_sum[wid] = sum;
        s_sumsq[wid] = sumsq;
    }
    __syncthreads();
    if (wid == 0) {
        float a = (lane < TPB / 32) ? s_sum[lane] : 0.0f;
        float b = (lane < TPB / 32) ? s_sumsq[lane] : 0.0f;
#pragma unroll
        for (int off = 8; off > 0; off >>= 1) {
            a += __shfl_xor_sync(0xffffffffu, a, off);
            b += __shfl_xor_sync(0xffffffffu, b, off);
        }
        if (lane == 0) {
            float mean = a * (1.0f / N_FEAT);
            float var = b * (1.0f / N_FEAT) - mean * mean;
            s_mean = mean;
            s_rstd = rsqrtf(var + EPS_F);
        }
    }
    __syncthreads();
    const float mean = s_mean;
    const float rstd = s_rstd;

    // Epilogue: x_hat * scale + shift
    const float4* scv = reinterpret_cast<const float4*>(g_scale);
    const float4* shv = reinterpret_cast<const float4*>(g_shift);
#pragma unroll
    for (int k = 0; k < VEC_PER_THREAD; k++) {
        int idx = tid + k * TPB;
        float4 sc = scv[idx];
        float4 sh = shv[idx];
        float4 t = v[k];
        float4 o;
        o.x = (t.x - mean) * rstd * sc.x + sh.x;
        o.y = (t.y - mean) * rstd * sc.y + sh.y;
        o.z = (t.z - mean) * rstd * sc.z + sh.z;
        o.w = (t.w - mean) * rstd * sc.w + sh.w;
        orow[idx] = o;
    }
}

// ---------------------------------------------------------------------------
extern "C" void kernel_launch(void* const* d_in, const int* in_sizes, int n_in,
                              void* d_out, int out_size) {
    const float* x = (const float*)d_in[0];
    const float* sA = (const float*)d_in[1];
    const float* sB = (const float*)d_in[2];
    const float* hA = (const float*)d_in[3];
    const float* hB = (const float*)d_in[4];
    float* out = (float*)d_out;

    compute_vectors_kernel<<<N_FEAT / 256, 256>>>(sA, sB, hA, hB);
    lora_layernorm_kernel<<<N_ROWS, TPB>>>(x, out);
}

// round 3
// speedup vs baseline: 1.0084x; 1.0061x over previous
#include <cuda_runtime.h>

// LoRALayerNorm: x [B=2, S=4096, N=8192] fp32
// scale[i] = SCALING * sum_r A_s[i,r] * B_s[r,i]
// shift[i] = SCALING * sum_r A_h[i,r] * B_h[r,i]
// out = layernorm(x, last dim) * scale + shift

#define N_FEAT 8192
#define N_ROWS 8192
#define RANK 4
#define SCALING_F 2.0f   // ALPHA/RANK = 8/4
#define EPS_F 1e-5f

#define TPB 512                 // threads per block (row kernel)
#define VEC_PER_THREAD 4        // 4 x float4 = 16 floats/thread; 512*16 = 8192

__device__ float g_scale[N_FEAT];
__device__ float g_shift[N_FEAT];

// ---------------------------------------------------------------------------
// Kernel 1: low-rank diagonal -> scale/shift vectors
// ---------------------------------------------------------------------------
__global__ void compute_vectors_kernel(const float* __restrict__ sA,
                                       const float* __restrict__ sB,
                                       const float* __restrict__ hA,
                                       const float* __restrict__ hB) {
    int i = blockIdx.x * blockDim.x + threadIdx.x;
    if (i >= N_FEAT) return;
    // A: [N, RANK] row-major; B: [RANK, N] row-major
    float4 a_s = *reinterpret_cast<const float4*>(sA + i * RANK);
    float4 a_h = *reinterpret_cast<const float4*>(hA + i * RANK);
    float sc = a_s.x * sB[0 * N_FEAT + i]
             + a_s.y * sB[1 * N_FEAT + i]
             + a_s.z * sB[2 * N_FEAT + i]
             + a_s.w * sB[3 * N_FEAT + i];
    float sh = a_h.x * hB[0 * N_FEAT + i]
             + a_h.y * hB[1 * N_FEAT + i]
             + a_h.z * hB[2 * N_FEAT + i]
             + a_h.w * hB[3 * N_FEAT + i];
    g_scale[i] = sc * SCALING_F;
    g_shift[i] = sh * SCALING_F;
}

// ---------------------------------------------------------------------------
// Kernel 2: one CTA per row, register-resident single-pass layernorm
// 3 resident CTAs/SM so memory stays saturated through the reduction barriers.
// x/out are touch-once -> streaming hints keep scale/shift hot in L2.
// ---------------------------------------------------------------------------
__global__ __launch_bounds__(TPB, 3)
void lora_layernorm_kernel(const float* __restrict__ x,
                           float* __restrict__ out) {
    const int row = blockIdx.x;
    const int tid = threadIdx.x;
    const float4* xrow = reinterpret_cast<const float4*>(x + (size_t)row * N_FEAT);
    float4* orow = reinterpret_cast<float4*>(out + (size_t)row * N_FEAT);

    // Load 4 float4 per thread (streaming), strided across the row.
    float4 v[VEC_PER_THREAD];
    float sum = 0.0f, sumsq = 0.0f;
#pragma unroll
    for (int k = 0; k < VEC_PER_THREAD; k++) {
        float4 t = __ldcs(&xrow[tid + k * TPB]);
        v[k] = t;
        sum += t.x + t.y + t.z + t.w;
        sumsq += t.x * t.x + t.y * t.y + t.z * t.z + t.w * t.w;
    }

    // Warp reduce
#pragma unroll
    for (int off = 16; off > 0; off >>= 1) {
        sum += __shfl_xor_sync(0xffffffffu, sum, off);
        sumsq += __shfl_xor_sync(0xffffffffu, sumsq, off);
    }

    __shared__ float s_sum[TPB / 32];
    __shared__ float s_sumsq[TPB / 32];
    __shared__ float s_mean, s_rstd;
    const int wid = tid >> 5;
    const int lane = tid & 31;
    if (lane == 0) {
        s_sum[wid] = sum;
        s_sumsq[wid] = sumsq;
    }
    __syncthreads();
    if (wid == 0) {
        float a = (lane < TPB / 32) ? s_sum[lane] : 0.0f;
        float b = (lane < TPB / 32) ? s_sumsq[lane] : 0.0f;
#pragma unroll
        for (int off = 8; off > 0; off >>= 1) {
            a += __shfl_xor_sync(0xffffffffu, a, off);
            b += __shfl_xor_sync(0xffffffffu, b, off);
        }
        if (lane == 0) {
            float mean = a * (1.0f / N_FEAT);
            float var = b * (1.0f / N_FEAT) - mean * mean;
            s_mean = mean;
            s_rstd = rsqrtf(var + EPS_F);
        }
    }
    __syncthreads();
    const float mean = s_mean;
    const float rstd = s_rstd;

    // Epilogue: x_hat * scale + shift (scale/shift stay L2-resident)
    const float4* scv = reinterpret_cast<const float4*>(g_scale);
    const float4* shv = reinterpret_cast<const float4*>(g_shift);
#pragma unroll
    for (int k = 0; k < VEC_PER_THREAD; k++) {
        int idx = tid + k * TPB;
        float4 sc = __ldg(&scv[idx]);
        float4 sh = __ldg(&shv[idx]);
        float4 t = v[k];
        float4 o;
        o.x = (t.x - mean) * rstd * sc.x + sh.x;
        o.y = (t.y - mean) * rstd * sc.y + sh.y;
        o.z = (t.z - mean) * rstd * sc.z + sh.z;
        o.w = (t.w - mean) * rstd * sc.w + sh.w;
        __stcs(&orow[idx], o);
    }
}

// ---------------------------------------------------------------------------
extern "C" void kernel_launch(void* const* d_in, const int* in_sizes, int n_in,
                              void* d_out, int out_size) {
    const float* x = (const float*)d_in[0];
    const float* sA = (const float*)d_in[1];
    const float* sB = (const float*)d_in[2];
    const float* hA = (const float*)d_in[3];
    const float* hB = (const float*)d_in[4];
    float* out = (float*)d_out;

    compute_vectors_kernel<<<N_FEAT / 256, 256>>>(sA, sB, hA, hB);
    lora_layernorm_kernel<<<N_ROWS, TPB>>>(x, out);
}